// round 5
// baseline (speedup 1.0000x reference)
#include <cuda_runtime.h>
#include <cstdint>

#define BATCH   4
#define NPTS    8192
#define THREADS 128
#define UPT     8              // i-points per thread
#define UP2     (UPT/2)        // packed pairs per thread
#define ITILE   (THREADS*UPT)  // 1024
#define ITILES  (NPTS/ITILE)   // 8
#define JCHUNKS 16
#define JCHUNK  (NPTS/JCHUNKS) // 512

// scratch: per-point min squared distance (float bits, atomicMin'able since >=0)
__device__ unsigned int g_min[2][BATCH][NPTS];

// ---------------- f32x2 packed helpers (sm_100+ PTX) ----------------
__device__ __forceinline__ unsigned long long pack2(float lo, float hi) {
    unsigned long long r;
    asm("mov.b64 %0, {%1, %2};" : "=l"(r)
        : "r"(__float_as_uint(lo)), "r"(__float_as_uint(hi)));
    return r;
}
__device__ __forceinline__ void unpack2(unsigned long long v, float& lo, float& hi) {
    unsigned int a, b;
    asm("mov.b64 {%0, %1}, %2;" : "=r"(a), "=r"(b) : "l"(v));
    lo = __uint_as_float(a); hi = __uint_as_float(b);
}
__device__ __forceinline__ unsigned long long addx2(unsigned long long a, unsigned long long b) {
    unsigned long long r;
    asm("add.rn.f32x2 %0, %1, %2;" : "=l"(r) : "l"(a), "l"(b));
    return r;
}
__device__ __forceinline__ unsigned long long mulx2(unsigned long long a, unsigned long long b) {
    unsigned long long r;
    asm("mul.rn.f32x2 %0, %1, %2;" : "=l"(r) : "l"(a), "l"(b));
    return r;
}
__device__ __forceinline__ unsigned long long fmax2(unsigned long long a, unsigned long long b,
                                                    unsigned long long c) {
    unsigned long long r;
    asm("fma.rn.f32x2 %0, %1, %2, %3;" : "=l"(r) : "l"(a), "l"(b), "l"(c));
    return r;
}

// ---------------- init scratch to +inf bits ----------------
__global__ void cd_init_kernel() {
    int i = blockIdx.x * blockDim.x + threadIdx.x;
    ((unsigned int*)g_min)[i] = 0x7f800000u;  // +inf
}

// ---------------- pairwise min pass (both directions) ----------------
__global__ void __launch_bounds__(THREADS)
cd_pair_kernel(const float* __restrict__ in1, const float* __restrict__ in2) {
    unsigned bx  = blockIdx.x;
    unsigned jc  = bx % JCHUNKS; bx /= JCHUNKS;
    unsigned it  = bx % ITILES;  bx /= ITILES;
    unsigned b   = bx % BATCH;   bx /= BATCH;
    unsigned dir = bx;  // 0: A=in1 (dist1), 1: A=in2 (dist0)

    const float* A = dir ? in2 : in1;  // cloud we compute mins FOR
    const float* C = dir ? in1 : in2;  // cloud we scan OVER

    // stage negated, pre-duplicated j-chunk in smem:
    //   sxy[j] = { (-x,-x), (-y,-y) }   (16B, one broadcast LDS.128)
    //   sz[j]  = (-z,-z)                (8B,  one broadcast LDS.64)
    __shared__ ulonglong2          sxy[JCHUNK];
    __shared__ unsigned long long  sz[JCHUNK];
    const float* cb = C + ((size_t)b * NPTS + (size_t)jc * JCHUNK) * 3;
    for (int j = threadIdx.x; j < JCHUNK; j += THREADS) {
        float y0 = -cb[j * 3 + 0], y1 = -cb[j * 3 + 1], y2 = -cb[j * 3 + 2];
        sxy[j] = make_ulonglong2(pack2(y0, y0), pack2(y1, y1));
        sz[j]  = pack2(y2, y2);
    }

    // this thread's UPT i-points, packed two-per-lane-pair per coordinate
    const float* ca = A + ((size_t)b * NPTS + (size_t)it * ITILE) * 3;
    float x0[UPT], x1[UPT], x2[UPT];
#pragma unroll
    for (int u = 0; u < UPT; u++) {
        int i = u * THREADS + threadIdx.x;
        x0[u] = ca[i * 3 + 0];
        x1[u] = ca[i * 3 + 1];
        x2[u] = ca[i * 3 + 2];
    }
    unsigned long long xp0[UP2], xp1[UP2], xp2[UP2];
#pragma unroll
    for (int p = 0; p < UP2; p++) {
        xp0[p] = pack2(x0[2 * p], x0[2 * p + 1]);
        xp1[p] = pack2(x1[2 * p], x1[2 * p + 1]);
        xp2[p] = pack2(x2[2 * p], x2[2 * p + 1]);
    }

    float mn[UPT];
#pragma unroll
    for (int u = 0; u < UPT; u++) mn[u] = 3.4e38f;

    __syncthreads();

#pragma unroll 4
    for (int j = 0; j < JCHUNK; j++) {
        ulonglong2 nxy = sxy[j];
        unsigned long long nz = sz[j];
#pragma unroll
        for (int p = 0; p < UP2; p++) {
            unsigned long long d0  = addx2(xp0[p], nxy.x);
            unsigned long long acc = mulx2(d0, d0);
            unsigned long long d1  = addx2(xp1[p], nxy.y);
            acc = fmax2(d1, d1, acc);
            unsigned long long d2  = addx2(xp2[p], nz);
            acc = fmax2(d2, d2, acc);
            float lo, hi;
            unpack2(acc, lo, hi);
            mn[2 * p]     = fminf(mn[2 * p], lo);
            mn[2 * p + 1] = fminf(mn[2 * p + 1], hi);
        }
    }

    unsigned int* gm = &g_min[dir][b][it * ITILE];
#pragma unroll
    for (int u = 0; u < UPT; u++)
        atomicMin(&gm[u * THREADS + threadIdx.x], __float_as_uint(mn[u]));
}

// ---------------- final sqrt + mean reduction ----------------
__global__ void cd_reduce_kernel(float* __restrict__ out) {
    __shared__ float warpsum[32];
    const unsigned int* gm = (const unsigned int*)g_min;
    float s = 0.0f;
    for (int i = threadIdx.x; i < 2 * BATCH * NPTS; i += blockDim.x)
        s += sqrtf(__uint_as_float(gm[i]));
    for (int o = 16; o; o >>= 1) s += __shfl_xor_sync(0xffffffffu, s, o);
    if ((threadIdx.x & 31) == 0) warpsum[threadIdx.x >> 5] = s;
    __syncthreads();
    if (threadIdx.x < 32) {
        float v = (threadIdx.x < (int)(blockDim.x >> 5)) ? warpsum[threadIdx.x] : 0.0f;
        for (int o = 16; o; o >>= 1) v += __shfl_xor_sync(0xffffffffu, v, o);
        // loss = (1/B) * sum_b [ mean_m dist0 + mean_n dist1 ]
        //      = (sum of all 2*B*NPTS sqrt-mins) / (B * NPTS)   since N == M
        if (threadIdx.x == 0) out[0] = v / ((float)BATCH * (float)NPTS);
    }
}

extern "C" void kernel_launch(void* const* d_in, const int* in_sizes, int n_in,
                              void* d_out, int out_size) {
    const float* in1 = (const float*)d_in[0];  // [B, N, 3]
    const float* in2 = (const float*)d_in[1];  // [B, M, 3]
    (void)in_sizes; (void)n_in; (void)out_size;

    cd_init_kernel<<<(2 * BATCH * NPTS) / 1024, 1024>>>();
    cd_pair_kernel<<<2 * BATCH * ITILES * JCHUNKS, THREADS>>>(in1, in2);
    cd_reduce_kernel<<<1, 1024>>>((float*)d_out);
}

// round 6
// speedup vs baseline: 1.3963x; 1.3963x over previous
#include <cuda_runtime.h>
#include <cstdint>

#define BATCH   4
#define NPTS    8192
#define THREADS 128
#define UPT     8              // i-points per thread
#define UP2     (UPT/2)        // packed pairs per thread
#define ITILE   (THREADS*UPT)  // 1024
#define ITILES  (NPTS/ITILE)   // 8
#define JCHUNKS 32
#define JCHUNK  (NPTS/JCHUNKS) // 256

// scratch: per-point min squared distance (float bits, atomicMin'able since >=0)
// index 0: dist1 (min over m, per n of cloud1) ; index 1: dist0 (min over n, per m of cloud2)
__device__ unsigned int g_min[2][BATCH][NPTS];

// ---------------- f32x2 packed helpers (sm_100+ PTX) ----------------
__device__ __forceinline__ unsigned long long pack2(float lo, float hi) {
    unsigned long long r;
    asm("mov.b64 %0, {%1, %2};" : "=l"(r)
        : "r"(__float_as_uint(lo)), "r"(__float_as_uint(hi)));
    return r;
}
__device__ __forceinline__ void unpack2(unsigned long long v, float& lo, float& hi) {
    unsigned int a, b;
    asm("mov.b64 {%0, %1}, %2;" : "=r"(a), "=r"(b) : "l"(v));
    lo = __uint_as_float(a); hi = __uint_as_float(b);
}
__device__ __forceinline__ unsigned long long addx2(unsigned long long a, unsigned long long b) {
    unsigned long long r;
    asm("add.rn.f32x2 %0, %1, %2;" : "=l"(r) : "l"(a), "l"(b));
    return r;
}
__device__ __forceinline__ unsigned long long mulx2(unsigned long long a, unsigned long long b) {
    unsigned long long r;
    asm("mul.rn.f32x2 %0, %1, %2;" : "=l"(r) : "l"(a), "l"(b));
    return r;
}
__device__ __forceinline__ unsigned long long fmax2(unsigned long long a, unsigned long long b,
                                                    unsigned long long c) {
    unsigned long long r;
    asm("fma.rn.f32x2 %0, %1, %2, %3;" : "=l"(r) : "l"(a), "l"(b), "l"(c));
    return r;
}

// ---------------- init scratch to +inf bits ----------------
__global__ void cd_init_kernel() {
    int i = blockIdx.x * blockDim.x + threadIdx.x;
    ((unsigned int*)g_min)[i] = 0x7f800000u;  // +inf
}

// ---------------- single-pass pairwise kernel: both directions from one D tile ----------------
__global__ void __launch_bounds__(THREADS)
cd_pair_kernel(const float* __restrict__ in1, const float* __restrict__ in2) {
    unsigned bx = blockIdx.x;
    unsigned jc = bx % JCHUNKS; bx /= JCHUNKS;
    unsigned it = bx % ITILES;  bx /= ITILES;
    unsigned b  = bx;

    // stage negated, pre-duplicated j-chunk (cloud2) in smem:
    //   sxy[j] = { (-x,-x), (-y,-y) }  (one broadcast LDS.128)
    //   sz[j]  = (-z,-z)               (one broadcast LDS.64)
    __shared__ ulonglong2          sxy[JCHUNK];
    __shared__ unsigned long long  sz[JCHUNK];
    __shared__ unsigned int        s_cmin[THREADS / 32][JCHUNK];  // per-warp col mins (bits)

    const float* cb = in2 + ((size_t)b * NPTS + (size_t)jc * JCHUNK) * 3;
    for (int j = threadIdx.x; j < JCHUNK; j += THREADS) {
        float y0 = -cb[j * 3 + 0], y1 = -cb[j * 3 + 1], y2 = -cb[j * 3 + 2];
        sxy[j] = make_ulonglong2(pack2(y0, y0), pack2(y1, y1));
        sz[j]  = pack2(y2, y2);
    }

    // this thread's UPT i-points of cloud1, packed two-per-lane-pair per coordinate
    const float* ca = in1 + ((size_t)b * NPTS + (size_t)it * ITILE) * 3;
    unsigned long long xp0[UP2], xp1[UP2], xp2[UP2];
#pragma unroll
    for (int p = 0; p < UP2; p++) {
        int i0 = (2 * p) * THREADS + threadIdx.x;
        int i1 = (2 * p + 1) * THREADS + threadIdx.x;
        xp0[p] = pack2(ca[i0 * 3 + 0], ca[i1 * 3 + 0]);
        xp1[p] = pack2(ca[i0 * 3 + 1], ca[i1 * 3 + 1]);
        xp2[p] = pack2(ca[i0 * 3 + 2], ca[i1 * 3 + 2]);
    }

    float mn[UPT];
#pragma unroll
    for (int u = 0; u < UPT; u++) mn[u] = 3.4e38f;

    const int w    = threadIdx.x >> 5;
    const int lane = threadIdx.x & 31;

    __syncthreads();

#pragma unroll 2
    for (int j = 0; j < JCHUNK; j++) {
        ulonglong2 nxy = sxy[j];
        unsigned long long nz = sz[j];
        float d[UPT];
#pragma unroll
        for (int p = 0; p < UP2; p++) {
            unsigned long long d0  = addx2(xp0[p], nxy.x);
            unsigned long long acc = mulx2(d0, d0);
            unsigned long long d1  = addx2(xp1[p], nxy.y);
            acc = fmax2(d1, d1, acc);
            unsigned long long d2  = addx2(xp2[p], nz);
            acc = fmax2(d2, d2, acc);
            unpack2(acc, d[2 * p], d[2 * p + 1]);
        }
        // row mins (dist1 for cloud1 points): 8 FMNMX
#pragma unroll
        for (int u = 0; u < UPT; u++) mn[u] = fminf(mn[u], d[u]);
        // col min (dist0 for this j): tree over this thread's 8 i's, then warp REDUX
        float t01 = fminf(d[0], d[1]), t23 = fminf(d[2], d[3]);
        float t45 = fminf(d[4], d[5]), t67 = fminf(d[6], d[7]);
        float t = fminf(fminf(t01, t23), fminf(t45, t67));
        unsigned int m = __reduce_min_sync(0xffffffffu, __float_as_uint(t));
        if (lane == 0) s_cmin[w][j] = m;
    }

    __syncthreads();

    // fold per-warp col mins + publish dist0 (cloud2 side)
    unsigned int* gcol = &g_min[1][b][jc * JCHUNK];
    for (int j = threadIdx.x; j < JCHUNK; j += THREADS) {
        unsigned int v = min(min(s_cmin[0][j], s_cmin[1][j]),
                             min(s_cmin[2][j], s_cmin[3][j]));
        atomicMin(&gcol[j], v);
    }

    // publish dist1 (cloud1 side)
    unsigned int* grow = &g_min[0][b][it * ITILE];
#pragma unroll
    for (int u = 0; u < UPT; u++)
        atomicMin(&grow[u * THREADS + threadIdx.x], __float_as_uint(mn[u]));
}

// ---------------- final sqrt + mean reduction ----------------
__global__ void cd_reduce_kernel(float* __restrict__ out) {
    __shared__ float warpsum[32];
    const unsigned int* gm = (const unsigned int*)g_min;
    float s = 0.0f;
    for (int i = threadIdx.x; i < 2 * BATCH * NPTS; i += blockDim.x)
        s += sqrtf(__uint_as_float(gm[i]));
    for (int o = 16; o; o >>= 1) s += __shfl_xor_sync(0xffffffffu, s, o);
    if ((threadIdx.x & 31) == 0) warpsum[threadIdx.x >> 5] = s;
    __syncthreads();
    if (threadIdx.x < 32) {
        float v = (threadIdx.x < (int)(blockDim.x >> 5)) ? warpsum[threadIdx.x] : 0.0f;
        for (int o = 16; o; o >>= 1) v += __shfl_xor_sync(0xffffffffu, v, o);
        // loss = (sum of all 2*B*NPTS sqrt-mins) / (B * NPTS)   since N == M
        if (threadIdx.x == 0) out[0] = v / ((float)BATCH * (float)NPTS);
    }
}

extern "C" void kernel_launch(void* const* d_in, const int* in_sizes, int n_in,
                              void* d_out, int out_size) {
    const float* in1 = (const float*)d_in[0];  // [B, N, 3]
    const float* in2 = (const float*)d_in[1];  // [B, M, 3]
    (void)in_sizes; (void)n_in; (void)out_size;

    cd_init_kernel<<<(2 * BATCH * NPTS) / 1024, 1024>>>();
    cd_pair_kernel<<<BATCH * ITILES * JCHUNKS, THREADS>>>(in1, in2);
    cd_reduce_kernel<<<1, 1024>>>((float*)d_out);
}

// round 9
// speedup vs baseline: 1.4758x; 1.0570x over previous
#include <cuda_runtime.h>
#include <cstdint>

#define BATCH   4
#define NPTS    8192
#define THREADS 128
#define UPT     8              // i-points per thread
#define UP2     (UPT/2)        // packed pairs per thread
#define ITILE   (THREADS*UPT)  // 1024
#define ITILES  (NPTS/ITILE)   // 8
#define JCHUNKS 32
#define JCHUNK  (NPTS/JCHUNKS) // 256

// scratch: per-point min squared distance (float bits; bitwise-min valid for >=0,
// and spurious negatives from cancellation sort ABOVE everything as unsigned -> ignored)
// index 0: dist1 (per n of cloud1) ; index 1: dist0 (per m of cloud2)
__device__ unsigned int g_min[2][BATCH][NPTS];

// ---------------- f32x2 packed helpers (sm_100+ PTX) ----------------
__device__ __forceinline__ unsigned long long pack2(float lo, float hi) {
    unsigned long long r;
    asm("mov.b64 %0, {%1, %2};" : "=l"(r)
        : "r"(__float_as_uint(lo)), "r"(__float_as_uint(hi)));
    return r;
}
__device__ __forceinline__ void unpack2(unsigned long long v, float& lo, float& hi) {
    unsigned int a, b;
    asm("mov.b64 {%0, %1}, %2;" : "=r"(a), "=r"(b) : "l"(v));
    lo = __uint_as_float(a); hi = __uint_as_float(b);
}
__device__ __forceinline__ unsigned long long addx2(unsigned long long a, unsigned long long b) {
    unsigned long long r;
    asm("add.rn.f32x2 %0, %1, %2;" : "=l"(r) : "l"(a), "l"(b));
    return r;
}
__device__ __forceinline__ unsigned long long fmax2(unsigned long long a, unsigned long long b,
                                                    unsigned long long c) {
    unsigned long long r;
    asm("fma.rn.f32x2 %0, %1, %2, %3;" : "=l"(r) : "l"(a), "l"(b), "l"(c));
    return r;
}

// ---------------- init scratch to +inf bits ----------------
__global__ void cd_init_kernel() {
    int i = blockIdx.x * blockDim.x + threadIdx.x;
    ((unsigned int*)g_min)[i] = 0x7f800000u;  // +inf
}

// ---------------- single-pass pairwise kernel: both directions from one D tile ----------------
// d^2(i,j) = (|x_i|^2 + |y_j|^2) + x_i . (-2 y_j)   — 4 packed fma-pipe ops per 2 pairs
__global__ void __launch_bounds__(THREADS)
cd_pair_kernel(const float* __restrict__ in1, const float* __restrict__ in2) {
    unsigned bx = blockIdx.x;
    unsigned jc = bx % JCHUNKS; bx /= JCHUNKS;
    unsigned it = bx % ITILES;  bx /= ITILES;
    unsigned b  = bx;

    // smem per j (cloud2): two 16B entries, each one broadcast LDS.128
    //   sA[j] = { (-2y0,-2y0), (-2y1,-2y1) }
    //   sB[j] = { (-2y2,-2y2), (ny,ny) }      ny = |y|^2
    __shared__ ulonglong2 sA[JCHUNK];
    __shared__ ulonglong2 sB[JCHUNK];
    __shared__ unsigned int s_cmin[THREADS / 32][JCHUNK];  // per-warp col mins (bits)

    const float* cb = in2 + ((size_t)b * NPTS + (size_t)jc * JCHUNK) * 3;
    for (int j = threadIdx.x; j < JCHUNK; j += THREADS) {
        float y0 = cb[j * 3 + 0], y1 = cb[j * 3 + 1], y2 = cb[j * 3 + 2];
        float ny = y0 * y0 + y1 * y1 + y2 * y2;
        sA[j] = make_ulonglong2(pack2(-2.f * y0, -2.f * y0), pack2(-2.f * y1, -2.f * y1));
        sB[j] = make_ulonglong2(pack2(-2.f * y2, -2.f * y2), pack2(ny, ny));
    }

    // this thread's UPT i-points of cloud1: packed coords + packed norms
    const float* ca = in1 + ((size_t)b * NPTS + (size_t)it * ITILE) * 3;
    unsigned long long xp0[UP2], xp1[UP2], xp2[UP2], nxp[UP2];
#pragma unroll
    for (int p = 0; p < UP2; p++) {
        int i0 = (2 * p) * THREADS + threadIdx.x;
        int i1 = (2 * p + 1) * THREADS + threadIdx.x;
        float a0 = ca[i0 * 3 + 0], a1 = ca[i0 * 3 + 1], a2 = ca[i0 * 3 + 2];
        float b0 = ca[i1 * 3 + 0], b1 = ca[i1 * 3 + 1], b2 = ca[i1 * 3 + 2];
        xp0[p] = pack2(a0, b0);
        xp1[p] = pack2(a1, b1);
        xp2[p] = pack2(a2, b2);
        nxp[p] = pack2(a0 * a0 + a1 * a1 + a2 * a2,
                       b0 * b0 + b1 * b1 + b2 * b2);
    }

    float mn[UPT];
#pragma unroll
    for (int u = 0; u < UPT; u++) mn[u] = 3.4e38f;

    const int w    = threadIdx.x >> 5;
    const int lane = threadIdx.x & 31;

    __syncthreads();

#pragma unroll 2
    for (int j = 0; j < JCHUNK; j++) {
        ulonglong2 ya = sA[j];   // (-2y0), (-2y1) duplicated
        ulonglong2 yb = sB[j];   // (-2y2), (ny)   duplicated
        float d[UPT];
#pragma unroll
        for (int p = 0; p < UP2; p++) {
            unsigned long long acc = addx2(nxp[p], yb.y);   // nx + ny
            acc = fmax2(xp0[p], ya.x, acc);                 // + x0*(-2y0)
            acc = fmax2(xp1[p], ya.y, acc);                 // + x1*(-2y1)
            acc = fmax2(xp2[p], yb.x, acc);                 // + x2*(-2y2)
            unpack2(acc, d[2 * p], d[2 * p + 1]);
        }
        // row mins (dist1 side): 8 FMNMX
#pragma unroll
        for (int u = 0; u < UPT; u++) mn[u] = fminf(mn[u], d[u]);
        // col min (dist0 side, this j): thread tree then warp REDUX (bitwise, >=0 or ignored-neg)
        float t01 = fminf(d[0], d[1]), t23 = fminf(d[2], d[3]);
        float t45 = fminf(d[4], d[5]), t67 = fminf(d[6], d[7]);
        float t = fminf(fminf(t01, t23), fminf(t45, t67));
        unsigned int m = __reduce_min_sync(0xffffffffu, __float_as_uint(t));
        if (lane == 0) s_cmin[w][j] = m;
    }

    __syncthreads();

    // fold per-warp col mins + publish dist0 (cloud2 side)
    unsigned int* gcol = &g_min[1][b][jc * JCHUNK];
    for (int j = threadIdx.x; j < JCHUNK; j += THREADS) {
        unsigned int v = min(min(s_cmin[0][j], s_cmin[1][j]),
                             min(s_cmin[2][j], s_cmin[3][j]));
        atomicMin(&gcol[j], v);
    }

    // publish dist1 (cloud1 side)
    unsigned int* grow = &g_min[0][b][it * ITILE];
#pragma unroll
    for (int u = 0; u < UPT; u++)
        atomicMin(&grow[u * THREADS + threadIdx.x], __float_as_uint(mn[u]));
}

// ---------------- final sqrt + mean reduction ----------------
__global__ void cd_reduce_kernel(float* __restrict__ out) {
    __shared__ float warpsum[32];
    const unsigned int* gm = (const unsigned int*)g_min;
    float s = 0.0f;
    for (int i = threadIdx.x; i < 2 * BATCH * NPTS; i += blockDim.x)
        s += sqrtf(fmaxf(__uint_as_float(gm[i]), 0.0f));  // clamp cancellation negatives
    for (int o = 16; o; o >>= 1) s += __shfl_xor_sync(0xffffffffu, s, o);
    if ((threadIdx.x & 31) == 0) warpsum[threadIdx.x >> 5] = s;
    __syncthreads();
    if (threadIdx.x < 32) {
        float v = (threadIdx.x < (int)(blockDim.x >> 5)) ? warpsum[threadIdx.x] : 0.0f;
        for (int o = 16; o; o >>= 1) v += __shfl_xor_sync(0xffffffffu, v, o);
        // loss = (sum of all 2*B*NPTS sqrt-mins) / (B * NPTS)   since N == M
        if (threadIdx.x == 0) out[0] = v / ((float)BATCH * (float)NPTS);
    }
}

extern "C" void kernel_launch(void* const* d_in, const int* in_sizes, int n_in,
                              void* d_out, int out_size) {
    const float* in1 = (const float*)d_in[0];  // [B, N, 3]
    const float* in2 = (const float*)d_in[1];  // [B, M, 3]
    (void)in_sizes; (void)n_in; (void)out_size;

    cd_init_kernel<<<(2 * BATCH * NPTS) / 1024, 1024>>>();
    cd_pair_kernel<<<BATCH * ITILES * JCHUNKS, THREADS>>>(in1, in2);
    cd_reduce_kernel<<<1, 1024>>>((float*)d_out);
}